// round 5
// baseline (speedup 1.0000x reference)
#include <cuda_runtime.h>

#define NROWS 50000
#define TILE  64
#define NBLK  ((NROWS + TILE - 1) / TILE)   // 782
#define XOFF  (NROWS * 64)                  // y starts here in d_out

// g_bw segment offsets: l0 rows (k*64+v) x 64w, l1 rows (k*32+v) x 32w, l2 rows (k*16+v) x 16w
#define BW1_OFF (64 * 64 * 64)              // 262144
#define BW2_OFF (BW1_OFF + 64 * 32 * 32)    // 327680
#define BW_TOT  (BW2_OFF + 64 * 16 * 16)    // 344064
#define FW_TOT  (5376 * 64)                 // 344064

// ---------------- device scratch (no runtime allocation allowed) ----------------
__device__ __align__(16) float g_h [NBLK * TILE * 64];
__device__ __align__(16) float g_dh[NBLK * TILE * 64];
__device__ __align__(16) float g_fw[FW_TOT];   // [j][k], j = global pair idx, 0.5*c_l*(W[u,v,k]+W[v,u,k])
__device__ __align__(16) float g_bw[BW_TOT];   // [(k,v)][w], c_l*(W[v,w,k]+W[w,v,k])

// ---------------- prep: fold path norms + symmetrize weights ----------------
__global__ void prep_w(const float* __restrict__ W0, const float* __restrict__ W1,
                       const float* __restrict__ W2) {
    const float C0 = rsqrtf(5376.0f);
    const float C1 = C0 * rsqrtf(3.0f);
    const float C2 = C0 * rsqrtf(5.0f);
    int idx = blockIdx.x * blockDim.x + threadIdx.x;
    if (idx < FW_TOT) {
        int j = idx >> 6, k = idx & 63;
        float v_;
        if (j < 4096) {
            int u = j >> 6, v = j & 63;
            v_ = 0.5f * C0 * (W0[(u * 64 + v) * 64 + k] + W0[(v * 64 + u) * 64 + k]);
        } else if (j < 5120) {
            int t = j - 4096, u = t >> 5, v = t & 31;
            v_ = 0.5f * C1 * (W1[(u * 32 + v) * 64 + k] + W1[(v * 32 + u) * 64 + k]);
        } else {
            int t = j - 5120, u = t >> 4, v = t & 15;
            v_ = 0.5f * C2 * (W2[(u * 16 + v) * 64 + k] + W2[(v * 16 + u) * 64 + k]);
        }
        g_fw[idx] = v_;
    } else if (idx < FW_TOT + BW_TOT) {
        int i = idx - FW_TOT;
        float v_;
        if (i < BW1_OFF) {
            int w = i & 63, r = i >> 6, k = r >> 6, v = r & 63;
            v_ = C0 * (W0[(v * 64 + w) * 64 + k] + W0[(w * 64 + v) * 64 + k]);
        } else if (i < BW2_OFF) {
            int t = i - BW1_OFF, w = t & 31, r = t >> 5, k = r >> 5, v = r & 31;
            v_ = C1 * (W1[(v * 32 + w) * 64 + k] + W1[(w * 32 + v) * 64 + k]);
        } else {
            int t = i - BW2_OFF, w = t & 15, r = t >> 4, k = r >> 4, v = r & 15;
            v_ = C2 * (W2[(v * 16 + w) * 64 + k] + W2[(w * 16 + v) * 64 + k]);
        }
        g_bw[i] = v_;
    }
}

// ---------------- K1: forward FCTP  h[64n,64k] = dot[64n,5376j] @ g_fw ----------------
#define XP 241
#define K1_SMEM ((64 * XP + 64 * 68 + 64 * 68) * 4)

__global__ void __launch_bounds__(256, 2) k1_fwd(const float* __restrict__ X) {
    extern __shared__ float sm1[];
    float* xs  = sm1;             // [64][XP]
    float* AsT = sm1 + 64 * XP;   // [64 j][68] -> [n]
    float* Bs  = AsT + 64 * 68;   // [64 j][68] -> [k]
    const int tid = threadIdx.x;
    const int bn  = blockIdx.x * 64;

    for (int i = tid; i < 64 * 240; i += 256) {
        int n = i / 240, c = i - n * 240;
        xs[n * XP + c] = (bn + n < NROWS) ? X[(bn + n) * 240 + c] : 0.f;
    }
    __syncthreads();

    const int cg = tid & 15, rg = tid >> 4;
    const int r0 = rg * 4, c0 = cg * 4;
    float acc[4][4];
#pragma unroll
    for (int i = 0; i < 4; i++)
#pragma unroll
        for (int j = 0; j < 4; j++) acc[i][j] = 0.f;

    for (int ch = 0; ch < 84; ++ch) {
#pragma unroll
        for (int q = 0; q < 4; ++q) {          // Bs[t][k] <- g_fw[(ch*64+t)*64+k]
            int f = tid + 256 * q;
            int t = f >> 4, kp = (f & 15) << 2;
            *(float4*)(Bs + t * 68 + kp) = *(const float4*)(g_fw + (ch * 64 + t) * 64 + kp);
        }
        if (ch < 64) {
            int u = ch;
#pragma unroll
            for (int q = 0; q < 16; ++q) {
                int idx = q * 256 + tid, n = idx & 63, v = idx >> 6;
                AsT[v * 68 + n] = xs[n * XP + u] * xs[n * XP + v];
            }
        } else if (ch < 80) {
            int cc = ch - 64;
#pragma unroll
            for (int q = 0; q < 16; ++q) {
                int idx = q * 256 + tid, n = idx & 63, t = idx >> 6;
                int j1 = cc * 64 + t, u = j1 >> 5, v = j1 & 31;
                const float* xr = xs + n * XP + 64;
                AsT[t * 68 + n] = xr[u * 3] * xr[v * 3]
                                + xr[u * 3 + 1] * xr[v * 3 + 1]
                                + xr[u * 3 + 2] * xr[v * 3 + 2];
            }
        } else {
            int cc = ch - 80;
#pragma unroll
            for (int q = 0; q < 16; ++q) {
                int idx = q * 256 + tid, n = idx & 63, t = idx >> 6;
                int j2 = cc * 64 + t, u = j2 >> 4, v = j2 & 15;
                const float* xr = xs + n * XP + 160;
                float s = xr[u * 5] * xr[v * 5];
                s += xr[u * 5 + 1] * xr[v * 5 + 1];
                s += xr[u * 5 + 2] * xr[v * 5 + 2];
                s += xr[u * 5 + 3] * xr[v * 5 + 3];
                s += xr[u * 5 + 4] * xr[v * 5 + 4];
                AsT[t * 68 + n] = s;
            }
        }
        __syncthreads();
#pragma unroll 8
        for (int kk = 0; kk < 64; ++kk) {
            float4 a = *(const float4*)(AsT + kk * 68 + r0);
            float4 b = *(const float4*)(Bs  + kk * 68 + c0);
            float av[4] = {a.x, a.y, a.z, a.w};
            float bv[4] = {b.x, b.y, b.z, b.w};
#pragma unroll
            for (int i = 0; i < 4; i++)
#pragma unroll
                for (int j = 0; j < 4; j++) acc[i][j] += av[i] * bv[j];
        }
        __syncthreads();
    }
#pragma unroll
    for (int i = 0; i < 4; i++) {
        int n = bn + r0 + i;
        if (n < NROWS)
            *(float4*)(g_h + (size_t)n * 64 + c0) =
                make_float4(acc[i][0], acc[i][1], acc[i][2], acc[i][3]);
    }
}

// ---------------- K2: MLP forward + backward (64 rows / block) ----------------
#define K2_SMEM ((8 * 64 * 65 + 64) * 4)
__global__ void __launch_bounds__(256) k2_mlp(const float* __restrict__ A1, const float* __restrict__ b1,
                                              const float* __restrict__ A2, const float* __restrict__ b2,
                                              const float* __restrict__ A3, const float* __restrict__ b3,
                                              float* __restrict__ Xout) {
    extern __shared__ float sm2[];
    float* A1s = sm2;                    // [o][65] -> i
    float* A2s = A1s + 64 * 65;
    float* A3s = A2s + 64 * 65;
    float* hs  = A3s + 64 * 65;          // [n][65]
    float* g1s = hs  + 64 * 65;
    float* d1s = g1s + 64 * 65;
    float* g2s = d1s + 64 * 65;
    float* d2s = g2s + 64 * 65;
    float* s3  = d2s + 64 * 65;          // [64]
    const int tid = threadIdx.x;
    const int bn  = blockIdx.x * 64;

    for (int i = tid; i < 4096; i += 256) {
        int o = i >> 6, c = i & 63;
        A1s[o * 65 + c] = A1[i];
        A2s[o * 65 + c] = A2[i];
        A3s[o * 65 + c] = A3[i];
    }
    for (int i = tid; i < 4096; i += 256) {
        int n = i >> 6, c = i & 63;
        hs[n * 65 + c] = (bn + n < NROWS) ? g_h[(size_t)(bn + n) * 64 + c] : 0.f;
    }
    __syncthreads();
    if (tid < 64) {
        float s = 0.f;
        for (int k = 0; k < 64; ++k) s += A3s[k * 65 + tid];
        s3[tid] = s;
    }
    __syncthreads();

    const int n  = tid & 63;
    const int o0 = (tid >> 6) * 16;
    const bool valid = (bn + n) < NROWS;

    // layer 1
#pragma unroll
    for (int oo = 0; oo < 16; ++oo) {
        int o = o0 + oo;
        float z = b1[o];
#pragma unroll 8
        for (int i = 0; i < 64; ++i) z += hs[n * 65 + i] * A1s[o * 65 + i];
        float sg = 1.f / (1.f + expf(-z));
        g1s[n * 65 + o] = z * sg;
        d1s[n * 65 + o] = sg * (1.f + z * (1.f - sg));
    }
    __syncthreads();
    // layer 2
#pragma unroll
    for (int oo = 0; oo < 16; ++oo) {
        int o = o0 + oo;
        float z = b2[o];
#pragma unroll 8
        for (int i = 0; i < 64; ++i) z += g1s[n * 65 + i] * A2s[o * 65 + i];
        float sg = 1.f / (1.f + expf(-z));
        g2s[n * 65 + o] = z * sg;
        d2s[n * 65 + o] = sg * (1.f + z * (1.f - sg));
    }
    __syncthreads();
    // layer 3 -> x output ; dz2 = s3 * silu'(z2) (in place)
#pragma unroll
    for (int oo = 0; oo < 16; ++oo) {
        int o = o0 + oo;
        float z = b3[o];
#pragma unroll 8
        for (int i = 0; i < 64; ++i) z += g2s[n * 65 + i] * A3s[o * 65 + i];
        if (valid) Xout[(size_t)(bn + n) * 64 + o] = z;
        d2s[n * 65 + o] = s3[o] * d2s[n * 65 + o];
    }
    __syncthreads();
    // dz1 = (dz2 @ A2) * silu'(z1)  -> store into g1s
#pragma unroll
    for (int oo = 0; oo < 16; ++oo) {
        int i = o0 + oo;
        float s = 0.f;
#pragma unroll 8
        for (int j = 0; j < 64; ++j) s += d2s[n * 65 + j] * A2s[j * 65 + i];
        g1s[n * 65 + i] = s * d1s[n * 65 + i];
    }
    __syncthreads();
    // dh = dz1 @ A1
#pragma unroll
    for (int oo = 0; oo < 16; ++oo) {
        int i = o0 + oo;
        float s = 0.f;
#pragma unroll 8
        for (int j = 0; j < 64; ++j) s += g1s[n * 65 + j] * A1s[j * 65 + i];
        if (valid) g_dh[(size_t)(bn + n) * 64 + i] = s;
    }
}

// ---------------- K3a: backward l=0  Y0[64n,64w] = A[64n,(k,v)] @ g_bw0 ----------------
#define K3A_SMEM ((64 * 65 + 64 * 65 + 64 * 68 + 64 * 68) * 4)
__global__ void __launch_bounds__(256, 3) k3a_bwd(const float* __restrict__ X,
                                                  float* __restrict__ out) {
    extern __shared__ float sm3[];
    float* xs0 = sm3;                // [n][65]
    float* dhs = xs0 + 64 * 65;      // [n][65]
    float* AT  = dhs + 64 * 65;      // [64 red][68] -> n
    float* Bs  = AT  + 64 * 68;      // [64 red][68] -> w
    const int tid = threadIdx.x;
    const int bn  = blockIdx.x * 64;

    for (int i = tid; i < 4096; i += 256) {
        int n = i >> 6, c = i & 63;
        bool v = (bn + n) < NROWS;
        xs0[n * 65 + c] = v ? X[(size_t)(bn + n) * 240 + c] : 0.f;
        dhs[n * 65 + c] = v ? g_dh[(size_t)(bn + n) * 64 + c] : 0.f;
    }
    __syncthreads();

    const int cg = tid & 15, rg = tid >> 4;
    const int r0 = rg * 4, c0 = cg * 4;
    float acc[4][4];
#pragma unroll
    for (int i = 0; i < 4; i++)
#pragma unroll
        for (int j = 0; j < 4; j++) acc[i][j] = 0.f;

    for (int ch = 0; ch < 64; ++ch) {          // ch = k
#pragma unroll
        for (int q = 0; q < 4; ++q) {
            int f = tid + 256 * q;
            int t = f >> 4, wp = (f & 15) << 2;
            *(float4*)(Bs + t * 68 + wp) = *(const float4*)(g_bw + (ch * 64 + t) * 64 + wp);
        }
#pragma unroll
        for (int q = 0; q < 16; ++q) {
            int idx = q * 256 + tid, n = idx & 63, v = idx >> 6;
            AT[v * 68 + n] = dhs[n * 65 + ch] * xs0[n * 65 + v];
        }
        __syncthreads();
#pragma unroll 8
        for (int kk = 0; kk < 64; ++kk) {
            float4 a = *(const float4*)(AT + kk * 68 + r0);
            float4 b = *(const float4*)(Bs + kk * 68 + c0);
            float av[4] = {a.x, a.y, a.z, a.w};
            float bv[4] = {b.x, b.y, b.z, b.w};
#pragma unroll
            for (int i = 0; i < 4; i++)
#pragma unroll
                for (int j = 0; j < 4; j++) acc[i][j] += av[i] * bv[j];
        }
        __syncthreads();
    }
#pragma unroll
    for (int i = 0; i < 4; i++) {
        int n = bn + r0 + i;
        if (n < NROWS)
            *(float4*)(out + XOFF + (size_t)n * 240 + c0) =
                make_float4(acc[i][0], acc[i][1], acc[i][2], acc[i][3]);
    }
}

// ---------------- K3b: backward l=1 (3 m) + l=2 (5 m) ----------------
#define XP2 177
#define K3B_SMEM ((64 * XP2 + 64 * 65 + 64 * 68 + 64 * 68) * 4)
__global__ void __launch_bounds__(256, 2) k3b_bwd(const float* __restrict__ X,
                                                  float* __restrict__ out) {
    extern __shared__ float sm4[];
    float* xs  = sm4;                // [n][XP2], cols 64..239 of X
    float* dhs = xs  + 64 * XP2;     // [n][65]
    float* AT  = dhs + 64 * 65;      // [64 red][68] -> n
    float* Bs  = AT  + 64 * 68;      // [64 red][68] -> w
    const int tid = threadIdx.x;
    const int bn  = blockIdx.x * 64;

    for (int i = tid; i < 64 * 176; i += 256) {
        int n = i / 176, c = i - n * 176;
        xs[n * XP2 + c] = (bn + n < NROWS) ? X[(size_t)(bn + n) * 240 + 64 + c] : 0.f;
    }
    for (int i = tid; i < 4096; i += 256) {
        int n = i >> 6, c = i & 63;
        dhs[n * 65 + c] = (bn + n < NROWS) ? g_dh[(size_t)(bn + n) * 64 + c] : 0.f;
    }
    __syncthreads();

    // ---- l=1: output 64n x 32w per m ----
    {
        const int cg = tid & 7, rg = tid >> 3;   // c0 = cg*4 (w), r0 = rg*2 (n)
        const int r0 = rg * 2, c0 = cg * 4;
        for (int m = 0; m < 3; ++m) {
            float acc[2][4];
#pragma unroll
            for (int i = 0; i < 2; i++)
#pragma unroll
                for (int j = 0; j < 4; j++) acc[i][j] = 0.f;
            for (int ch = 0; ch < 32; ++ch) {
#pragma unroll
                for (int q = 0; q < 2; ++q) {      // Bs[t][w], 64x32
                    int f = tid + 256 * q;
                    int t = f >> 3, wp = (f & 7) << 2;
                    *(float4*)(Bs + t * 68 + wp) =
                        *(const float4*)(g_bw + BW1_OFF + (ch * 64 + t) * 32 + wp);
                }
#pragma unroll
                for (int q = 0; q < 16; ++q) {     // AT[t][n]
                    int idx = q * 256 + tid, n = idx & 63, t = idx >> 6;
                    int k = 2 * ch + (t >> 5), v = t & 31;
                    AT[t * 68 + n] = dhs[n * 65 + k] * xs[n * XP2 + v * 3 + m];
                }
                __syncthreads();
#pragma unroll 8
                for (int kk = 0; kk < 64; ++kk) {
                    float a0 = AT[kk * 68 + r0];
                    float a1 = AT[kk * 68 + r0 + 1];
                    float4 b = *(const float4*)(Bs + kk * 68 + c0);
                    acc[0][0] += a0 * b.x; acc[0][1] += a0 * b.y;
                    acc[0][2] += a0 * b.z; acc[0][3] += a0 * b.w;
                    acc[1][0] += a1 * b.x; acc[1][1] += a1 * b.y;
                    acc[1][2] += a1 * b.z; acc[1][3] += a1 * b.w;
                }
                __syncthreads();
            }
#pragma unroll
            for (int i = 0; i < 2; i++) {
                int n = bn + r0 + i;
                if (n < NROWS) {
#pragma unroll
                    for (int j = 0; j < 4; j++)
                        out[XOFF + (size_t)n * 240 + 64 + (c0 + j) * 3 + m] = acc[i][j];
                }
            }
        }
    }

    // ---- l=2: output 64n x 16w per m ----
    {
        const int nn = tid >> 2;                 // one n per thread
        const int c0 = (tid & 3) * 4;
        for (int m = 0; m < 5; ++m) {
            float acc[4] = {0.f, 0.f, 0.f, 0.f};
            for (int ch = 0; ch < 16; ++ch) {
                {                                  // Bs[t][w], 64x16 = 1024
                    int t = tid >> 2, wp = (tid & 3) << 2;
                    *(float4*)(Bs + t * 68 + wp) =
                        *(const float4*)(g_bw + BW2_OFF + (ch * 64 + t) * 16 + wp);
                }
#pragma unroll
                for (int q = 0; q < 16; ++q) {
                    int idx = q * 256 + tid, n = idx & 63, t = idx >> 6;
                    int k = 4 * ch + (t >> 4), v = t & 15;
                    AT[t * 68 + n] = dhs[n * 65 + k] * xs[n * XP2 + 96 + v * 5 + m];
                }
                __syncthreads();
#pragma unroll 8
                for (int kk = 0; kk < 64; ++kk) {
                    float a = AT[kk * 68 + nn];
                    float4 b = *(const float4*)(Bs + kk * 68 + c0);
                    acc[0] += a * b.x; acc[1] += a * b.y;
                    acc[2] += a * b.z; acc[3] += a * b.w;
                }
                __syncthreads();
            }
            int n = bn + nn;
            if (n < NROWS) {
#pragma unroll
                for (int j = 0; j < 4; j++)
                    out[XOFF + (size_t)n * 240 + 160 + (c0 + j) * 5 + m] = acc[j];
            }
        }
    }
}

// ---------------- launch ----------------
extern "C" void kernel_launch(void* const* d_in, const int* in_sizes, int n_in,
                              void* d_out, int out_size) {
    const float* X  = (const float*)d_in[0];
    const float* W0 = (const float*)d_in[1];
    const float* W1 = (const float*)d_in[2];
    const float* W2 = (const float*)d_in[3];
    const float* A1 = (const float*)d_in[4];
    const float* b1 = (const float*)d_in[5];
    const float* A2 = (const float*)d_in[6];
    const float* b2 = (const float*)d_in[7];
    const float* A3 = (const float*)d_in[8];
    const float* b3 = (const float*)d_in[9];
    float* out = (float*)d_out;

    cudaFuncSetAttribute(k1_fwd,  cudaFuncAttributeMaxDynamicSharedMemorySize, K1_SMEM);
    cudaFuncSetAttribute(k2_mlp,  cudaFuncAttributeMaxDynamicSharedMemorySize, K2_SMEM);
    cudaFuncSetAttribute(k3a_bwd, cudaFuncAttributeMaxDynamicSharedMemorySize, K3A_SMEM);
    cudaFuncSetAttribute(k3b_bwd, cudaFuncAttributeMaxDynamicSharedMemorySize, K3B_SMEM);

    prep_w<<<(FW_TOT + BW_TOT + 255) / 256, 256>>>(W0, W1, W2);
    k1_fwd<<<NBLK, 256, K1_SMEM>>>(X);
    k2_mlp<<<NBLK, 256, K2_SMEM>>>(A1, b1, A2, b2, A3, b3, out);
    k3a_bwd<<<NBLK, 256, K3A_SMEM>>>(X, out);
    k3b_bwd<<<NBLK, 256, K3B_SMEM>>>(X, out);
}

// round 6
// speedup vs baseline: 2.0332x; 2.0332x over previous
#include <cuda_runtime.h>

#define NROWS 50000
#define NBLK  782
#define XOFF  (NROWS * 64)
#define BW1_OFF (64 * 64 * 64)
#define BW2_OFF (BW1_OFF + 64 * 1024)
#define BW_TOT  (BW2_OFF + 64 * 256)
#define FW_TOT  (5376 * 64)
#define Q 68

__device__ __align__(16) float g_h [NBLK * 64 * 64];
__device__ __align__(16) float g_dh[NBLK * 64 * 64];
__device__ __align__(16) float g_fw[FW_TOT];  // fwd [j][k]; l0 part triangular-folded
__device__ __align__(16) float g_bw[BW_TOT];  // bwd; l0 [(k,v)][w]; l1 [k][v*32+w]; l2 [k][v*16+w]

#define MM44(a4, b4) { \
    acc[0][0]+=a4.x*b4.x; acc[0][1]+=a4.x*b4.y; acc[0][2]+=a4.x*b4.z; acc[0][3]+=a4.x*b4.w; \
    acc[1][0]+=a4.y*b4.x; acc[1][1]+=a4.y*b4.y; acc[1][2]+=a4.y*b4.z; acc[1][3]+=a4.y*b4.w; \
    acc[2][0]+=a4.z*b4.x; acc[2][1]+=a4.z*b4.y; acc[2][2]+=a4.z*b4.z; acc[2][3]+=a4.z*b4.w; \
    acc[3][0]+=a4.w*b4.x; acc[3][1]+=a4.w*b4.y; acc[3][2]+=a4.w*b4.z; acc[3][3]+=a4.w*b4.w; }
#define ZACC { for (int i_=0;i_<4;i_++) for (int j_=0;j_<4;j_++) acc[i_][j_]=0.f; }

// ---------------- prep ----------------
__global__ void prep_w(const float* __restrict__ W0, const float* __restrict__ W1,
                       const float* __restrict__ W2) {
    const float C0 = rsqrtf(5376.0f);
    const float C1 = C0 * rsqrtf(3.0f);
    const float C2 = C0 * rsqrtf(5.0f);
    int idx = blockIdx.x * blockDim.x + threadIdx.x;
    if (idx < FW_TOT) {
        int j = idx >> 6, k = idx & 63;
        float v_;
        if (j < 4096) {
            int u = j >> 6, v = j & 63;
            if (u < v)       v_ = C0 * (W0[(u*64+v)*64+k] + W0[(v*64+u)*64+k]);
            else if (u == v) v_ = C0 * W0[(u*64+u)*64+k];
            else             v_ = 0.f;
        } else if (j < 5120) {
            int t = j - 4096, u = t >> 5, v = t & 31;
            v_ = 0.5f * C1 * (W1[(u*32+v)*64+k] + W1[(v*32+u)*64+k]);
        } else {
            int t = j - 5120, u = t >> 4, v = t & 15;
            v_ = 0.5f * C2 * (W2[(u*16+v)*64+k] + W2[(v*16+u)*64+k]);
        }
        g_fw[idx] = v_;
    } else if (idx < FW_TOT + BW_TOT) {
        int i = idx - FW_TOT;
        float v_;
        if (i < BW1_OFF) {
            int w = i & 63, r = i >> 6, k = r >> 6, v = r & 63;
            v_ = C0 * (W0[(v*64+w)*64+k] + W0[(w*64+v)*64+k]);
        } else if (i < BW2_OFF) {
            int t = i - BW1_OFF, w = t & 31, r = t >> 5, k = r >> 5, v = r & 31;
            v_ = C1 * (W1[(v*32+w)*64+k] + W1[(w*32+v)*64+k]);
        } else {
            int t = i - BW2_OFF, w = t & 15, r = t >> 4, k = r >> 4, v = r & 15;
            v_ = C2 * (W2[(v*16+w)*64+k] + W2[(w*16+v)*64+k]);
        }
        g_bw[i] = v_;
    }
}

// ---------------- K1: forward FCTP ----------------
#define K1_SMEM ((240 * Q + 64 * Q + 64 * Q) * 4)
__global__ void __launch_bounds__(256, 2) k1_fwd(const float* __restrict__ X) {
    extern __shared__ float sm[];
    float* xsT = sm;             // [240 c][Q] -> n
    float* AT  = sm + 240 * Q;   // [64 t][Q]
    float* Bs  = sm + 304 * Q;   // [64 t][Q] -> k
    const int tid = threadIdx.x, bn = blockIdx.x * 64;

    for (int i = tid; i < 240 * 64; i += 256) {
        int n = i / 240, c = i - n * 240;
        xsT[c * Q + n] = (bn + n < NROWS) ? X[(size_t)(bn + n) * 240 + c] : 0.f;
    }
    __syncthreads();
    const int cg = tid & 15, rg = tid >> 4, r0 = rg * 4, c0 = cg * 4;
    float acc[4][4]; ZACC;

    // l0 triangular, rank-1 A
    for (int u = 0; u < 64; ++u) {
#pragma unroll
        for (int q = 0; q < 4; ++q) {
            int f = tid + 256 * q, t = f >> 4, kp = (f & 15) << 2;
            if (t >= u)
                *(float4*)(Bs + t * Q + kp) = *(const float4*)(g_fw + (u * 64 + t) * 64 + kp);
        }
        float4 xu = *(const float4*)(xsT + u * Q + r0);
        __syncthreads();
#pragma unroll 4
        for (int kk = u; kk < 64; ++kk) {
            float4 a = *(const float4*)(xsT + kk * Q + r0);
            float4 b = *(const float4*)(Bs + kk * Q + c0);
            float4 av = make_float4(xu.x * a.x, xu.y * a.y, xu.z * a.z, xu.w * a.w);
            MM44(av, b);
        }
        __syncthreads();
    }
    // l1: 16 chunks
    for (int ch = 0; ch < 16; ++ch) {
#pragma unroll
        for (int q = 0; q < 4; ++q) {
            int f = tid + 256 * q, t = f >> 4, kp = (f & 15) << 2;
            *(float4*)(Bs + t * Q + kp) = *(const float4*)(g_fw + (4096 + ch * 64 + t) * 64 + kp);
        }
#pragma unroll
        for (int q = 0; q < 16; ++q) {
            int idx = q * 256 + tid, n = idx & 63, t = idx >> 6;
            int j1 = ch * 64 + t, u = j1 >> 5, v = j1 & 31;
            const float* xu_ = xsT + (64 + u * 3) * Q + n;
            const float* xv_ = xsT + (64 + v * 3) * Q + n;
            AT[t * Q + n] = xu_[0] * xv_[0] + xu_[Q] * xv_[Q] + xu_[2 * Q] * xv_[2 * Q];
        }
        __syncthreads();
#pragma unroll 8
        for (int kk = 0; kk < 64; ++kk) {
            float4 a = *(const float4*)(AT + kk * Q + r0);
            float4 b = *(const float4*)(Bs + kk * Q + c0);
            MM44(a, b);
        }
        __syncthreads();
    }
    // l2: 4 chunks
    for (int ch = 0; ch < 4; ++ch) {
#pragma unroll
        for (int q = 0; q < 4; ++q) {
            int f = tid + 256 * q, t = f >> 4, kp = (f & 15) << 2;
            *(float4*)(Bs + t * Q + kp) = *(const float4*)(g_fw + (5120 + ch * 64 + t) * 64 + kp);
        }
#pragma unroll
        for (int q = 0; q < 16; ++q) {
            int idx = q * 256 + tid, n = idx & 63, t = idx >> 6;
            int j2 = ch * 64 + t, u = j2 >> 4, v = j2 & 15;
            const float* xu_ = xsT + (160 + u * 5) * Q + n;
            const float* xv_ = xsT + (160 + v * 5) * Q + n;
            float s = xu_[0] * xv_[0] + xu_[Q] * xv_[Q] + xu_[2 * Q] * xv_[2 * Q]
                    + xu_[3 * Q] * xv_[3 * Q] + xu_[4 * Q] * xv_[4 * Q];
            AT[t * Q + n] = s;
        }
        __syncthreads();
#pragma unroll 8
        for (int kk = 0; kk < 64; ++kk) {
            float4 a = *(const float4*)(AT + kk * Q + r0);
            float4 b = *(const float4*)(Bs + kk * Q + c0);
            MM44(a, b);
        }
        __syncthreads();
    }
#pragma unroll
    for (int i = 0; i < 4; ++i) {
        int n = bn + r0 + i;
        if (n < NROWS)
            *(float4*)(g_h + (size_t)n * 64 + c0) =
                make_float4(acc[i][0], acc[i][1], acc[i][2], acc[i][3]);
    }
}

// ---------------- K2: MLP fwd+bwd, register tiled ----------------
#define K2_SMEM ((10 * 64 * Q + 64) * 4)
__global__ void __launch_bounds__(256) k2_mlp(const float* __restrict__ A1, const float* __restrict__ b1,
                                              const float* __restrict__ A2, const float* __restrict__ b2,
                                              const float* __restrict__ A3, const float* __restrict__ b3,
                                              float* __restrict__ Xout) {
    extern __shared__ float sm[];
    float* A1T = sm;                // [i][o]
    float* A2T = sm + 64 * Q;
    float* A3T = sm + 2 * 64 * Q;
    float* A1s = sm + 3 * 64 * Q;   // [o][i] (row-major copies)
    float* A2s = sm + 4 * 64 * Q;
    float* hT  = sm + 5 * 64 * Q;   // [feat][n]
    float* g1T = sm + 6 * 64 * Q;
    float* d1T = sm + 7 * 64 * Q;
    float* g2T = sm + 8 * 64 * Q;
    float* d2T = sm + 9 * 64 * Q;
    float* s3  = sm + 10 * 64 * Q;
    const int tid = threadIdx.x, bn = blockIdx.x * 64;

    for (int i = tid; i < 4096; i += 256) {
        int o = i >> 6, c = i & 63;
        float w1 = A1[i], w2 = A2[i], w3 = A3[i];
        A1s[o * Q + c] = w1; A2s[o * Q + c] = w2;
        A1T[c * Q + o] = w1; A2T[c * Q + o] = w2; A3T[c * Q + o] = w3;
    }
    for (int i = tid; i < 4096; i += 256) {
        int n = i >> 6, c = i & 63;
        hT[c * Q + n] = (bn + n < NROWS) ? g_h[(size_t)(bn + n) * 64 + c] : 0.f;
    }
    __syncthreads();
    if (tid < 64) {
        float s = 0.f;
        for (int k = 0; k < 64; ++k) s += A3T[tid * Q + k];
        s3[tid] = s;
    }
    __syncthreads();

    const int cg = tid & 15, rg = tid >> 4, o0 = cg * 4, n0 = rg * 4;
    float acc[4][4];

    // L1
    ZACC;
#pragma unroll 8
    for (int kk = 0; kk < 64; ++kk) {
        float4 a = *(const float4*)(hT + kk * Q + n0);
        float4 b = *(const float4*)(A1T + kk * Q + o0);
        MM44(a, b);
    }
#pragma unroll
    for (int j = 0; j < 4; ++j) {
        float bb = b1[o0 + j];
        float g[4], d[4];
#pragma unroll
        for (int i = 0; i < 4; i++) {
            float z = acc[i][j] + bb;
            float sg = 1.f / (1.f + expf(-z));
            g[i] = z * sg;
            d[i] = sg * (1.f + z * (1.f - sg));
        }
        *(float4*)(g1T + (o0 + j) * Q + n0) = make_float4(g[0], g[1], g[2], g[3]);
        *(float4*)(d1T + (o0 + j) * Q + n0) = make_float4(d[0], d[1], d[2], d[3]);
    }
    __syncthreads();
    // L2 (dz2 = s3*silu'(z2) folded into d2T)
    ZACC;
#pragma unroll 8
    for (int kk = 0; kk < 64; ++kk) {
        float4 a = *(const float4*)(g1T + kk * Q + n0);
        float4 b = *(const float4*)(A2T + kk * Q + o0);
        MM44(a, b);
    }
#pragma unroll
    for (int j = 0; j < 4; ++j) {
        float bb = b2[o0 + j], sc = s3[o0 + j];
        float g[4], d[4];
#pragma unroll
        for (int i = 0; i < 4; i++) {
            float z = acc[i][j] + bb;
            float sg = 1.f / (1.f + expf(-z));
            g[i] = z * sg;
            d[i] = sc * sg * (1.f + z * (1.f - sg));
        }
        *(float4*)(g2T + (o0 + j) * Q + n0) = make_float4(g[0], g[1], g[2], g[3]);
        *(float4*)(d2T + (o0 + j) * Q + n0) = make_float4(d[0], d[1], d[2], d[3]);
    }
    __syncthreads();
    // L3 -> Xout
    ZACC;
#pragma unroll 8
    for (int kk = 0; kk < 64; ++kk) {
        float4 a = *(const float4*)(g2T + kk * Q + n0);
        float4 b = *(const float4*)(A3T + kk * Q + o0);
        MM44(a, b);
    }
#pragma unroll
    for (int i = 0; i < 4; ++i) {
        int n = bn + n0 + i;
        if (n < NROWS)
            *(float4*)(Xout + (size_t)n * 64 + o0) =
                make_float4(acc[i][0] + b3[o0], acc[i][1] + b3[o0 + 1],
                            acc[i][2] + b3[o0 + 2], acc[i][3] + b3[o0 + 3]);
    }
    // L4: dz1 = (dz2 @ A2) * silu'(z1) -> g1T (no reader of g1T between syncs)
    ZACC;
#pragma unroll 8
    for (int kk = 0; kk < 64; ++kk) {
        float4 a = *(const float4*)(d2T + kk * Q + n0);
        float4 b = *(const float4*)(A2s + kk * Q + o0);
        MM44(a, b);
    }
#pragma unroll
    for (int j = 0; j < 4; ++j) {
        float4 d = *(const float4*)(d1T + (o0 + j) * Q + n0);
        *(float4*)(g1T + (o0 + j) * Q + n0) =
            make_float4(acc[0][j] * d.x, acc[1][j] * d.y, acc[2][j] * d.z, acc[3][j] * d.w);
    }
    __syncthreads();
    // L5: dh = dz1 @ A1 -> g_dh
    ZACC;
#pragma unroll 8
    for (int kk = 0; kk < 64; ++kk) {
        float4 a = *(const float4*)(g1T + kk * Q + n0);
        float4 b = *(const float4*)(A1s + kk * Q + o0);
        MM44(a, b);
    }
#pragma unroll
    for (int i = 0; i < 4; ++i) {
        int n = bn + n0 + i;
        if (n < NROWS)
            *(float4*)(g_dh + (size_t)n * 64 + o0) =
                make_float4(acc[i][0], acc[i][1], acc[i][2], acc[i][3]);
    }
}

// ---------------- K3a: backward l=0, rank-1 A ----------------
#define K3A_SMEM ((3 * 64 * Q) * 4)
__global__ void __launch_bounds__(256, 3) k3a_bwd(const float* __restrict__ X,
                                                  float* __restrict__ out) {
    extern __shared__ float sm[];
    float* xsT = sm;              // [v][Q] -> n (X cols 0..63)
    float* dhT = sm + 64 * Q;     // [k][Q] -> n
    float* Bs  = sm + 2 * 64 * Q; // [v][Q] -> w
    const int tid = threadIdx.x, bn = blockIdx.x * 64;

    for (int i = tid; i < 4096; i += 256) {
        int n = i >> 6, c = i & 63;
        bool ok = (bn + n) < NROWS;
        xsT[c * Q + n] = ok ? X[(size_t)(bn + n) * 240 + c] : 0.f;
        dhT[c * Q + n] = ok ? g_dh[(size_t)(bn + n) * 64 + c] : 0.f;
    }
    __syncthreads();
    const int cg = tid & 15, rg = tid >> 4, r0 = rg * 4, c0 = cg * 4;
    float acc[4][4]; ZACC;

    for (int ch = 0; ch < 64; ++ch) {       // ch = k
#pragma unroll
        for (int q = 0; q < 4; ++q) {
            int f = tid + 256 * q, t = f >> 4, wp = (f & 15) << 2;
            *(float4*)(Bs + t * Q + wp) = *(const float4*)(g_bw + (ch * 64 + t) * 64 + wp);
        }
        float4 dh4 = *(const float4*)(dhT + ch * Q + r0);
        __syncthreads();
#pragma unroll 8
        for (int kk = 0; kk < 64; ++kk) {
            float4 a = *(const float4*)(xsT + kk * Q + r0);
            float4 b = *(const float4*)(Bs + kk * Q + c0);
            float4 av = make_float4(dh4.x * a.x, dh4.y * a.y, dh4.z * a.z, dh4.w * a.w);
            MM44(av, b);
        }
        __syncthreads();
    }
#pragma unroll
    for (int i = 0; i < 4; ++i) {
        int n = bn + r0 + i;
        if (n < NROWS)
            *(float4*)(out + XOFF + (size_t)n * 240 + c0) =
                make_float4(acc[i][0], acc[i][1], acc[i][2], acc[i][3]);
    }
}

// ---------------- K3b: backward l=1,2 via G = dh @ BW then apply ----------------
#define K3B_SMEM ((176 * Q + 64 * Q + 64 * Q + 64 * Q) * 4)
__global__ void __launch_bounds__(256, 2) k3b_bwd(const float* __restrict__ X,
                                                  float* __restrict__ out) {
    extern __shared__ float sm[];
    float* xsT = sm;               // [176 c][Q] -> n (X cols 64..239)
    float* dhT = sm + 176 * Q;     // [k][Q]
    float* Bs  = sm + 240 * Q;     // [k][Q] -> 64 cols of BW chunk
    float* Gs  = sm + 304 * Q;     // [col][Q] -> n
    const int tid = threadIdx.x, bn = blockIdx.x * 64;

    for (int i = tid; i < 176 * 64; i += 256) {
        int n = i / 176, c = i - n * 176;
        xsT[c * Q + n] = (bn + n < NROWS) ? X[(size_t)(bn + n) * 240 + 64 + c] : 0.f;
    }
    for (int i = tid; i < 4096; i += 256) {
        int n = i >> 6, c = i & 63;
        dhT[c * Q + n] = (bn + n < NROWS) ? g_dh[(size_t)(bn + n) * 64 + c] : 0.f;
    }
    __syncthreads();
    const int cg = tid & 15, rg = tid >> 4, r0 = rg * 4, c0 = cg * 4;
    const int an = tid & 63, ag = tid >> 6;   // apply mapping: n, group
    float acc[4][4];

    // ---- l1: 16 chunks (each = v-pair {2ch,2ch+1} x 32 w) ----
    {
        float y1[8][3];
#pragma unroll
        for (int a = 0; a < 8; a++)
#pragma unroll
            for (int m = 0; m < 3; m++) y1[a][m] = 0.f;
        for (int ch = 0; ch < 16; ++ch) {
#pragma unroll
            for (int q = 0; q < 4; ++q) {
                int f = tid + 256 * q, t = f >> 4, wp = (f & 15) << 2;
                *(float4*)(Bs + t * Q + wp) =
                    *(const float4*)(g_bw + BW1_OFF + t * 1024 + ch * 64 + wp);
            }
            __syncthreads();
            ZACC;
#pragma unroll 8
            for (int kk = 0; kk < 64; ++kk) {
                float4 a = *(const float4*)(dhT + kk * Q + r0);
                float4 b = *(const float4*)(Bs + kk * Q + c0);
                MM44(a, b);
            }
#pragma unroll
            for (int j = 0; j < 4; ++j)
                *(float4*)(Gs + (c0 + j) * Q + r0) =
                    make_float4(acc[0][j], acc[1][j], acc[2][j], acc[3][j]);
            __syncthreads();
            float xa[3], xb[3];
#pragma unroll
            for (int m = 0; m < 3; m++) {
                xa[m] = xsT[((2 * ch) * 3 + m) * Q + an];
                xb[m] = xsT[((2 * ch + 1) * 3 + m) * Q + an];
            }
#pragma unroll
            for (int ww = 0; ww < 8; ++ww) {
                int w = ag * 8 + ww;
                float g0 = Gs[w * Q + an];
                float g1 = Gs[(32 + w) * Q + an];
#pragma unroll
                for (int m = 0; m < 3; m++) y1[ww][m] += g0 * xa[m] + g1 * xb[m];
            }
            __syncthreads();
        }
        if (bn + an < NROWS) {
#pragma unroll
            for (int ww = 0; ww < 8; ++ww)
#pragma unroll
                for (int m = 0; m < 3; m++)
                    out[XOFF + (size_t)(bn + an) * 240 + 64 + (ag * 8 + ww) * 3 + m] = y1[ww][m];
        }
    }
    // ---- l2: 4 chunks (each = v-quad {4ch..4ch+3} x 16 w) ----
    {
        float y2[4][5];
#pragma unroll
        for (int a = 0; a < 4; a++)
#pragma unroll
            for (int m = 0; m < 5; m++) y2[a][m] = 0.f;
        for (int ch = 0; ch < 4; ++ch) {
#pragma unroll
            for (int q = 0; q < 4; ++q) {
                int f = tid + 256 * q, t = f >> 4, wp = (f & 15) << 2;
                *(float4*)(Bs + t * Q + wp) =
                    *(const float4*)(g_bw + BW2_OFF + t * 256 + ch * 64 + wp);
            }
            __syncthreads();
            ZACC;
#pragma unroll 8
            for (int kk = 0; kk < 64; ++kk) {
                float4 a = *(const float4*)(dhT + kk * Q + r0);
                float4 b = *(const float4*)(Bs + kk * Q + c0);
                MM44(a, b);
            }
#pragma unroll
            for (int j = 0; j < 4; ++j)
                *(float4*)(Gs + (c0 + j) * Q + r0) =
                    make_float4(acc[0][j], acc[1][j], acc[2][j], acc[3][j]);
            __syncthreads();
            float xv[4][5];
#pragma unroll
            for (int vv = 0; vv < 4; vv++)
#pragma unroll
                for (int m = 0; m < 5; m++)
                    xv[vv][m] = xsT[(96 + (4 * ch + vv) * 5 + m) * Q + an];
#pragma unroll
            for (int ww = 0; ww < 4; ++ww) {
                int w = ag * 4 + ww;
#pragma unroll
                for (int vv = 0; vv < 4; vv++) {
                    float g = Gs[(vv * 16 + w) * Q + an];
#pragma unroll
                    for (int m = 0; m < 5; m++) y2[ww][m] += g * xv[vv][m];
                }
            }
            __syncthreads();
        }
        if (bn + an < NROWS) {
#pragma unroll
            for (int ww = 0; ww < 4; ++ww)
#pragma unroll
                for (int m = 0; m < 5; m++)
                    out[XOFF + (size_t)(bn + an) * 240 + 160 + (ag * 4 + ww) * 5 + m] = y2[ww][m];
        }
    }
}

// ---------------- launch ----------------
extern "C" void kernel_launch(void* const* d_in, const int* in_sizes, int n_in,
                              void* d_out, int out_size) {
    const float* X  = (const float*)d_in[0];
    const float* W0 = (const float*)d_in[1];
    const float* W1 = (const float*)d_in[2];
    const float* W2 = (const float*)d_in[3];
    const float* A1 = (const float*)d_in[4];
    const float* b1 = (const float*)d_in[5];
    const float* A2 = (const float*)d_in[6];
    const float* b2 = (const float*)d_in[7];
    const float* A3 = (const float*)d_in[8];
    const float* b3 = (const float*)d_in[9];
    float* out = (float*)d_out;

    cudaFuncSetAttribute(k1_fwd,  cudaFuncAttributeMaxDynamicSharedMemorySize, K1_SMEM);
    cudaFuncSetAttribute(k2_mlp,  cudaFuncAttributeMaxDynamicSharedMemorySize, K2_SMEM);
    cudaFuncSetAttribute(k3a_bwd, cudaFuncAttributeMaxDynamicSharedMemorySize, K3A_SMEM);
    cudaFuncSetAttribute(k3b_bwd, cudaFuncAttributeMaxDynamicSharedMemorySize, K3B_SMEM);

    prep_w<<<(FW_TOT + BW_TOT + 255) / 256, 256>>>(W0, W1, W2);
    k1_fwd<<<NBLK, 256, K1_SMEM>>>(X);
    k2_mlp<<<NBLK, 256, K2_SMEM>>>(A1, b1, A2, b2, A3, b3, out);
    k3a_bwd<<<NBLK, 256, K3A_SMEM>>>(X, out);
    k3b_bwd<<<NBLK, 256, K3B_SMEM>>>(X, out);
}